// round 4
// baseline (speedup 1.0000x reference)
#include <cuda_runtime.h>

// Problem constants
#define Bb 64
#define Nn 197
#define Dd 768
#define Hh 12
#define HDd 64
#define MROWS (Bb * Nn)          // 12608
#define NTAB 30                  // 2*MAX_REL+2 table rows
#define SCALE 0.125f

// ---------------------------------------------------------------------------
// Scratch (device globals; no allocation allowed). Kernels reference these
// directly — no cudaGetSymbolAddress anywhere.
// ---------------------------------------------------------------------------
__device__ float g_q[Bb * Hh * Nn * HDd];   // (B,H,N,HD)
__device__ float g_k[Bb * Hh * Nn * HDd];
__device__ float g_v[Bb * Hh * Nn * HDd];
__device__ float g_o[MROWS * Dd];           // (B*N, H*HD) row-major

// ---------------------------------------------------------------------------
// SGEMM: C[M,768] = A[M,768] @ B[768,768] + bias
// mode 0: A = g_o,     C = Cout (row-major)          [output projection]
// mode 1: A = Aptr_in, C = g_q scattered (B,H,N,HD)  [Q projection]
// mode 2: A = Aptr_in, C = g_k scattered             [K projection]
// mode 3: A = Aptr_in, C = g_v scattered             [V projection]
// ---------------------------------------------------------------------------
__global__ __launch_bounds__(256) void sgemm_kernel(
    const float* __restrict__ Aptr_in, const float* __restrict__ Bm,
    const float* __restrict__ bias, float* __restrict__ Cout,
    int M, int mode)
{
    const int K = 768, NC = 768;
    __shared__ float As[8][128];
    __shared__ float Bs[8][128];

    const float* A = (mode == 0) ? g_o : Aptr_in;

    const int tid = threadIdx.x;
    const int m0 = blockIdx.y * 128;
    const int n0 = blockIdx.x * 128;
    const int tx = tid & 15;         // col group
    const int ty = tid >> 4;         // row group

    const int arow  = tid >> 1;          // 0..127
    const int acol4 = (tid & 1) * 4;     // 0 or 4
    const int brow  = tid >> 5;          // 0..7
    const int bcol4 = (tid & 31) * 4;    // 0..124

    const bool a_ok = (m0 + arow) < M;
    const float* Aptr = A + (size_t)(m0 + arow) * K + acol4;
    const float* Bptr = Bm + (size_t)brow * NC + n0 + bcol4;

    float acc[8][8];
    #pragma unroll
    for (int i = 0; i < 8; i++)
        #pragma unroll
        for (int j = 0; j < 8; j++) acc[i][j] = 0.f;

    for (int k0 = 0; k0 < K; k0 += 8) {
        float4 av = a_ok ? *(const float4*)Aptr : make_float4(0.f, 0.f, 0.f, 0.f);
        float4 bv = *(const float4*)Bptr;
        __syncthreads();
        As[acol4 + 0][arow] = av.x;
        As[acol4 + 1][arow] = av.y;
        As[acol4 + 2][arow] = av.z;
        As[acol4 + 3][arow] = av.w;
        *(float4*)&Bs[brow][bcol4] = bv;
        __syncthreads();
        #pragma unroll
        for (int kk = 0; kk < 8; kk++) {
            float a[8], b[8];
            *(float4*)(a)     = *(const float4*)&As[kk][ty * 8];
            *(float4*)(a + 4) = *(const float4*)&As[kk][ty * 8 + 4];
            *(float4*)(b)     = *(const float4*)&Bs[kk][tx * 8];
            *(float4*)(b + 4) = *(const float4*)&Bs[kk][tx * 8 + 4];
            #pragma unroll
            for (int i = 0; i < 8; i++)
                #pragma unroll
                for (int j = 0; j < 8; j++)
                    acc[i][j] += a[i] * b[j];
        }
        Aptr += 8;
        Bptr += (size_t)8 * NC;
    }

    float* scatter_dst = (mode == 1) ? g_q : (mode == 2) ? g_k : g_v;

    #pragma unroll
    for (int i = 0; i < 8; i++) {
        int m = m0 + ty * 8 + i;
        if (m >= M) continue;
        if (mode == 0) {
            float* crow = Cout + (size_t)m * NC;
            #pragma unroll
            for (int j = 0; j < 8; j++) {
                int c = n0 + tx * 8 + j;
                crow[c] = acc[i][j] + bias[c];
            }
        } else {
            int bidx = m / Nn, n = m % Nn;
            #pragma unroll
            for (int j = 0; j < 8; j++) {
                int c = n0 + tx * 8 + j;
                int h = c >> 6, d = c & 63;
                scatter_dst[(((size_t)bidx * Hh + h) * Nn + n) * HDd + d] = acc[i][j] + bias[c];
            }
        }
    }
}

// ---------------------------------------------------------------------------
// Attention kernel: one CTA per (b,h), warp-per-query
// smem rows padded to stride 68 floats (conflict-free LDS.128 / LDS.64)
// ---------------------------------------------------------------------------
#define KV_STRIDE 68
#define SMEM_FLOATS (2 * Nn * KV_STRIDE + 4 * NTAB * KV_STRIDE + 8 * 64 + 8 * 208 + 4 * 8 * 32)

__global__ __launch_bounds__(256) void attn_kernel(
    const float* __restrict__ rkv, const float* __restrict__ rkh,
    const float* __restrict__ rvv, const float* __restrict__ rvh)
{
    extern __shared__ float sm[];
    float* Ks    = sm;                        // 197*68
    float* Vs    = Ks + Nn * KV_STRIDE;       // 197*68
    float* rkv_s = Vs + Nn * KV_STRIDE;       // 30*68 each
    float* rkh_s = rkv_s + NTAB * KV_STRIDE;
    float* rvv_s = rkh_s + NTAB * KV_STRIDE;
    float* rvh_s = rvv_s + NTAB * KV_STRIDE;
    float* qs    = rvh_s + NTAB * KV_STRIDE;  // 8*64
    float* ps    = qs + 8 * 64;               // 8*208
    float* qv_s  = ps + 8 * 208;              // 8*32 x4
    float* qh_s  = qv_s + 8 * 32;
    float* sv_s  = qh_s + 8 * 32;
    float* sh_s  = sv_s + 8 * 32;

    const int bh   = blockIdx.x;              // b*12 + h
    const int tid  = threadIdx.x;
    const int warp = tid >> 5, lane = tid & 31;
    const size_t base = (size_t)bh * Nn * HDd;
    const int b = bh / Hh, h = bh % Hh;

    // Stage K, V, tables
    for (int idx = tid; idx < Nn * HDd; idx += 256) {
        int j = idx >> 6, d = idx & 63;
        Ks[j * KV_STRIDE + d] = g_k[base + idx];
        Vs[j * KV_STRIDE + d] = g_v[base + idx];
    }
    for (int idx = tid; idx < NTAB * HDd; idx += 256) {
        int t = idx >> 6, d = idx & 63;
        rkv_s[t * KV_STRIDE + d] = rkv[idx];
        rkh_s[t * KV_STRIDE + d] = rkh[idx];
        rvv_s[t * KV_STRIDE + d] = rvv[idx];
        rvh_s[t * KV_STRIDE + d] = rvh[idx];
    }
    __syncthreads();

    float* qw  = qs + warp * 64;
    float* pw  = ps + warp * 208;
    float* qvw = qv_s + warp * 32;
    float* qhw = qh_s + warp * 32;
    float* svw = sv_s + warp * 32;
    float* shw = sh_s + warp * 32;

    for (int i = warp; i < Nn; i += 8) {
        // load query into per-warp smem, then registers
        const float* qg = g_q + base + (size_t)i * HDd;
        qw[lane]      = qg[lane];
        qw[lane + 32] = qg[lane + 32];
        __syncwarp();

        float4 qreg[16];
        #pragma unroll
        for (int d4 = 0; d4 < 16; d4++) qreg[d4] = ((const float4*)qw)[d4];

        // per-query table projections qv[t] = q . rel_k_v[t], qh likewise
        if (lane < NTAB) {
            float av = 0.f, ah = 0.f;
            const float4* tv4 = (const float4*)(rkv_s + lane * KV_STRIDE);
            const float4* th4 = (const float4*)(rkh_s + lane * KV_STRIDE);
            #pragma unroll
            for (int d4 = 0; d4 < 16; d4++) {
                float4 q4 = qreg[d4], v4 = tv4[d4], h4 = th4[d4];
                av += q4.x * v4.x + q4.y * v4.y + q4.z * v4.z + q4.w * v4.w;
                ah += q4.x * h4.x + q4.y * h4.y + q4.z * h4.z + q4.w * h4.w;
            }
            qvw[lane] = av;
            qhw[lane] = ah;
        }
        __syncwarp();

        const int iv_i = (i == 0) ? 0 : (i - 1) / 14;
        const int ih_i = (i == 0) ? 0 : (i - 1) % 14;

        // scores for this query across all keys (lane-parallel over j)
        float s[7];
        float mx = -1e30f;
        #pragma unroll
        for (int jj = 0; jj < 7; jj++) {
            int j = lane + jj * 32;
            if (j < Nn) {
                const float4* k4 = (const float4*)(Ks + j * KV_STRIDE);
                float acc = 0.f;
                #pragma unroll
                for (int d4 = 0; d4 < 16; d4++) {
                    float4 q4 = qreg[d4], kk4 = k4[d4];
                    acc += q4.x * kk4.x + q4.y * kk4.y + q4.z * kk4.z + q4.w * kk4.w;
                }
                int tv, th;
                if (i == 0 || j == 0) { tv = 0; th = 0; }
                else { int rj = j - 1; tv = rj / 14 - iv_i + 15; th = rj % 14 - ih_i + 15; }
                acc += qvw[tv] + qhw[th];
                s[jj] = acc * SCALE;
                mx = fmaxf(mx, s[jj]);
            } else s[jj] = -1e30f;
        }
        #pragma unroll
        for (int o = 16; o >= 1; o >>= 1) mx = fmaxf(mx, __shfl_xor_sync(0xffffffffu, mx, o));

        float sum = 0.f;
        #pragma unroll
        for (int jj = 0; jj < 7; jj++) {
            int j = lane + jj * 32;
            if (j < Nn) { s[jj] = __expf(s[jj] - mx); sum += s[jj]; }
            else s[jj] = 0.f;
        }
        #pragma unroll
        for (int o = 16; o >= 1; o >>= 1) sum += __shfl_xor_sync(0xffffffffu, sum, o);
        const float inv = 1.0f / sum;

        #pragma unroll
        for (int jj = 0; jj < 7; jj++) {
            int j = lane + jj * 32;
            if (j < Nn) pw[j] = s[jj] * inv;
        }
        __syncwarp();

        // deterministic bin sums for the value bias.
        // IDX_V(i, .) is constant over contiguous runs of 14; IDX_H(i, .) is 14-periodic.
        if (i == 0) {
            if (lane < NTAB) { svw[lane] = 0.f; shw[lane] = 0.f; }
            if (lane == 0) { svw[0] = 1.0f; shw[0] = 1.0f; }   // softmax row sums to 1
        } else if (lane < NTAB) {
            float sv = 0.f, sh = 0.f;
            int g = lane - 15 + iv_i;       // tv == lane  <=>  (j-1)/14 == g
            if (g >= 0 && g < 14) {
                int j0 = 14 * g + 1;
                #pragma unroll
                for (int u = 0; u < 14; u++) sv += pw[j0 + u];
            }
            int m = lane - 15 + ih_i;       // th == lane  <=>  (j-1)%14 == m
            if (m >= 0 && m < 14) {
                #pragma unroll
                for (int u = 0; u < 14; u++) sh += pw[1 + m + 14 * u];
            }
            if (lane == 0) { sv += pw[0]; sh += pw[0]; }   // j=0 -> bin 0 for both
            svw[lane] = sv;
            shw[lane] = sh;
        }
        __syncwarp();

        // output: each lane owns d = 2*lane, 2*lane+1
        float2 o = make_float2(0.f, 0.f);
        #pragma unroll 4
        for (int j = 0; j < Nn; j++) {
            float p = pw[j];
            float2 vv = *(const float2*)(Vs + j * KV_STRIDE + 2 * lane);
            o.x += p * vv.x;
            o.y += p * vv.y;
        }
        #pragma unroll
        for (int t = 0; t < NTAB; t++) {
            float a = svw[t], c = shw[t];
            float2 vv = *(const float2*)(rvv_s + t * KV_STRIDE + 2 * lane);
            float2 hh = *(const float2*)(rvh_s + t * KV_STRIDE + 2 * lane);
            o.x += a * vv.x + c * hh.x;
            o.y += a * vv.y + c * hh.y;
        }
        size_t orow = ((size_t)(b * Nn + i)) * Dd + h * HDd;
        *(float2*)(g_o + orow + 2 * lane) = o;
        __syncwarp();
    }
}

// ---------------------------------------------------------------------------
// Launch: kernel launches + one idempotent attribute set. Nothing else.
// ---------------------------------------------------------------------------
extern "C" void kernel_launch(void* const* d_in, const int* in_sizes, int n_in,
                              void* d_out, int out_size) {
    (void)in_sizes; (void)n_in; (void)out_size;
    const float* x   = (const float*)d_in[0];
    const float* wq  = (const float*)d_in[1];
    const float* bq  = (const float*)d_in[2];
    const float* wk  = (const float*)d_in[3];
    const float* bk  = (const float*)d_in[4];
    const float* wv  = (const float*)d_in[5];
    const float* bv  = (const float*)d_in[6];
    const float* wp  = (const float*)d_in[7];
    const float* bp  = (const float*)d_in[8];
    const float* rkv = (const float*)d_in[9];
    const float* rkh = (const float*)d_in[10];
    const float* rvv = (const float*)d_in[11];
    const float* rvh = (const float*)d_in[12];

    dim3 grid(Dd / 128, (MROWS + 127) / 128);  // (6, 99)
    dim3 block(256);
    sgemm_kernel<<<grid, block>>>(x, wq, bq, nullptr, MROWS, 1);
    sgemm_kernel<<<grid, block>>>(x, wk, bk, nullptr, MROWS, 2);
    sgemm_kernel<<<grid, block>>>(x, wv, bv, nullptr, MROWS, 3);

    size_t smem = (size_t)SMEM_FLOATS * sizeof(float);
    cudaFuncSetAttribute(attn_kernel, cudaFuncAttributeMaxDynamicSharedMemorySize, (int)smem);
    attn_kernel<<<Bb * Hh, 256, smem>>>(rkv, rkh, rvv, rvh);

    sgemm_kernel<<<grid, block>>>(nullptr, wp, bp, (float*)d_out, MROWS, 0);
}

// round 5
// speedup vs baseline: 1.0162x; 1.0162x over previous
#include <cuda_runtime.h>

// Problem constants
#define Bb 64
#define Nn 197
#define Dd 768
#define Hh 12
#define HDd 64
#define MROWS (Bb * Nn)          // 12608
#define NTAB 30                  // 2*MAX_REL+2 table rows
#define SCALE 0.125f

// ---------------------------------------------------------------------------
// Scratch (device globals; no allocation allowed)
// ---------------------------------------------------------------------------
__device__ float g_q[Bb * Hh * Nn * HDd];   // (B,H,N,HD)
__device__ float g_k[Bb * Hh * Nn * HDd];
__device__ float g_v[Bb * Hh * Nn * HDd];
__device__ float g_o[MROWS * Dd];           // (B*N, H*HD) row-major

// ---------------------------------------------------------------------------
// SGEMM: C[M,768] = A[M,768] @ B[768,768] + bias  (double-buffered smem)
// mode 0: A = g_o,  C = Cout row-major             [output projection]
// mode 1/2/3: A = Aptr_in, C = g_q/g_k/g_v scattered to (B,H,N,HD)
// ---------------------------------------------------------------------------
__global__ __launch_bounds__(256) void sgemm_kernel(
    const float* __restrict__ Aptr_in, const float* __restrict__ Bm,
    const float* __restrict__ bias, float* __restrict__ Cout,
    int M, int mode)
{
    const int K = 768, NC = 768;
    __shared__ float As[2][8][128];
    __shared__ float Bs[2][8][128];

    const float* A = (mode == 0) ? g_o : Aptr_in;

    const int tid = threadIdx.x;
    const int m0 = blockIdx.y * 128;
    const int n0 = blockIdx.x * 128;
    const int tx = tid & 15;         // col group
    const int ty = tid >> 4;         // row group

    const int arow  = tid >> 1;          // 0..127
    const int acol4 = (tid & 1) * 4;     // 0 or 4
    const int brow  = tid >> 5;          // 0..7
    const int bcol4 = (tid & 31) * 4;    // 0..124

    const bool a_ok = (m0 + arow) < M;
    const float* Aptr = A + (size_t)(m0 + arow) * K + acol4;
    const float* Bptr = Bm + (size_t)brow * NC + n0 + bcol4;

    float acc[8][8];
    #pragma unroll
    for (int i = 0; i < 8; i++)
        #pragma unroll
        for (int j = 0; j < 8; j++) acc[i][j] = 0.f;

    // prologue: fill buffer 0
    {
        float4 av = a_ok ? *(const float4*)Aptr : make_float4(0.f, 0.f, 0.f, 0.f);
        float4 bv = *(const float4*)Bptr;
        As[0][acol4 + 0][arow] = av.x;
        As[0][acol4 + 1][arow] = av.y;
        As[0][acol4 + 2][arow] = av.z;
        As[0][acol4 + 3][arow] = av.w;
        *(float4*)&Bs[0][brow][bcol4] = bv;
    }
    __syncthreads();

    int cur = 0;
    for (int k0 = 8; k0 <= K; k0 += 8) {
        float4 av, bv;
        const bool more = (k0 < K);
        if (more) {
            av = a_ok ? *(const float4*)(Aptr + k0) : make_float4(0.f, 0.f, 0.f, 0.f);
            bv = *(const float4*)(Bptr + (size_t)k0 * NC);
        }
        #pragma unroll
        for (int kk = 0; kk < 8; kk++) {
            float a[8], b[8];
            *(float4*)(a)     = *(const float4*)&As[cur][kk][ty * 8];
            *(float4*)(a + 4) = *(const float4*)&As[cur][kk][ty * 8 + 4];
            *(float4*)(b)     = *(const float4*)&Bs[cur][kk][tx * 8];
            *(float4*)(b + 4) = *(const float4*)&Bs[cur][kk][tx * 8 + 4];
            #pragma unroll
            for (int i = 0; i < 8; i++)
                #pragma unroll
                for (int j = 0; j < 8; j++)
                    acc[i][j] += a[i] * b[j];
        }
        if (more) {
            int nxt = cur ^ 1;
            As[nxt][acol4 + 0][arow] = av.x;
            As[nxt][acol4 + 1][arow] = av.y;
            As[nxt][acol4 + 2][arow] = av.z;
            As[nxt][acol4 + 3][arow] = av.w;
            *(float4*)&Bs[nxt][brow][bcol4] = bv;
            __syncthreads();
            cur = nxt;
        }
    }

    float* scatter_dst = (mode == 1) ? g_q : (mode == 2) ? g_k : g_v;

    #pragma unroll
    for (int i = 0; i < 8; i++) {
        int m = m0 + ty * 8 + i;
        if (m >= M) continue;
        if (mode == 0) {
            float* crow = Cout + (size_t)m * NC;
            #pragma unroll
            for (int j = 0; j < 8; j++) {
                int c = n0 + tx * 8 + j;
                crow[c] = acc[i][j] + bias[c];
            }
        } else {
            int bidx = m / Nn, n = m % Nn;
            #pragma unroll
            for (int j = 0; j < 8; j++) {
                int c = n0 + tx * 8 + j;
                int h = c >> 6, d = c & 63;
                scatter_dst[(((size_t)bidx * Hh + h) * Nn + n) * HDd + d] = acc[i][j] + bias[c];
            }
        }
    }
}

// ---------------------------------------------------------------------------
// Attention kernel: one CTA per (b,h), 16 warps, warp-per-query
// smem rows padded to stride 68 floats (conflict-free LDS.128 / LDS.64)
// ---------------------------------------------------------------------------
#define NW 16
#define KV_STRIDE 68
#define SMEM_FLOATS (2 * Nn * KV_STRIDE + 4 * NTAB * KV_STRIDE + NW * 64 + NW * 208 + 4 * NW * 32)

__global__ __launch_bounds__(32 * NW) void attn_kernel(
    const float* __restrict__ rkv, const float* __restrict__ rkh,
    const float* __restrict__ rvv, const float* __restrict__ rvh)
{
    extern __shared__ float sm[];
    float* Ks    = sm;                        // 197*68
    float* Vs    = Ks + Nn * KV_STRIDE;       // 197*68
    float* rkv_s = Vs + Nn * KV_STRIDE;       // 30*68 each
    float* rkh_s = rkv_s + NTAB * KV_STRIDE;
    float* rvv_s = rkh_s + NTAB * KV_STRIDE;
    float* rvh_s = rvv_s + NTAB * KV_STRIDE;
    float* qs    = rvh_s + NTAB * KV_STRIDE;  // NW*64
    float* ps    = qs + NW * 64;              // NW*208
    float* qv_s  = ps + NW * 208;             // NW*32 x4
    float* qh_s  = qv_s + NW * 32;
    float* sv_s  = qh_s + NW * 32;
    float* sh_s  = sv_s + NW * 32;

    const int bh   = blockIdx.x;              // b*12 + h
    const int tid  = threadIdx.x;
    const int warp = tid >> 5, lane = tid & 31;
    const size_t base = (size_t)bh * Nn * HDd;
    const int b = bh / Hh, h = bh % Hh;

    // Stage K, V, tables
    for (int idx = tid; idx < Nn * HDd; idx += 32 * NW) {
        int j = idx >> 6, d = idx & 63;
        Ks[j * KV_STRIDE + d] = g_k[base + idx];
        Vs[j * KV_STRIDE + d] = g_v[base + idx];
    }
    for (int idx = tid; idx < NTAB * HDd; idx += 32 * NW) {
        int t = idx >> 6, d = idx & 63;
        rkv_s[t * KV_STRIDE + d] = rkv[idx];
        rkh_s[t * KV_STRIDE + d] = rkh[idx];
        rvv_s[t * KV_STRIDE + d] = rvv[idx];
        rvh_s[t * KV_STRIDE + d] = rvh[idx];
    }
    __syncthreads();

    float* qw  = qs + warp * 64;
    float* pw  = ps + warp * 208;
    float* qvw = qv_s + warp * 32;
    float* qhw = qh_s + warp * 32;
    float* svw = sv_s + warp * 32;
    float* shw = sh_s + warp * 32;

    const int half = lane >> 4;        // 0 or 1 (split-warp for V/table loops)
    const int dl   = (lane & 15) * 4;  // d offset, float4 granularity

    for (int i = warp; i < Nn; i += NW) {
        // load query into per-warp smem, then registers
        const float* qg = g_q + base + (size_t)i * HDd;
        qw[lane]      = qg[lane];
        qw[lane + 32] = qg[lane + 32];
        __syncwarp();

        float4 qreg[16];
        #pragma unroll
        for (int d4 = 0; d4 < 16; d4++) qreg[d4] = ((const float4*)qw)[d4];

        // per-query table projections qv[t] = q . rel_k_v[t], qh likewise
        if (lane < NTAB) {
            float av = 0.f, ah = 0.f;
            const float4* tv4 = (const float4*)(rkv_s + lane * KV_STRIDE);
            const float4* th4 = (const float4*)(rkh_s + lane * KV_STRIDE);
            #pragma unroll
            for (int d4 = 0; d4 < 16; d4++) {
                float4 q4 = qreg[d4], v4 = tv4[d4], h4 = th4[d4];
                av += q4.x * v4.x + q4.y * v4.y + q4.z * v4.z + q4.w * v4.w;
                ah += q4.x * h4.x + q4.y * h4.y + q4.z * h4.z + q4.w * h4.w;
            }
            qvw[lane] = av;
            qhw[lane] = ah;
        }
        __syncwarp();

        const int iv_i = (i == 0) ? 0 : (i - 1) / 14;
        const int ih_i = (i == 0) ? 0 : (i - 1) % 14;

        // scores for this query across all keys (lane-parallel over j)
        float s[7];
        float mx = -1e30f;
        #pragma unroll
        for (int jj = 0; jj < 7; jj++) {
            int j = lane + jj * 32;
            if (j < Nn) {
                const float4* k4 = (const float4*)(Ks + j * KV_STRIDE);
                float acc = 0.f;
                #pragma unroll
                for (int d4 = 0; d4 < 16; d4++) {
                    float4 q4 = qreg[d4], kk4 = k4[d4];
                    acc += q4.x * kk4.x + q4.y * kk4.y + q4.z * kk4.z + q4.w * kk4.w;
                }
                int tv, th;
                if (i == 0 || j == 0) { tv = 0; th = 0; }
                else { int rj = j - 1; tv = rj / 14 - iv_i + 15; th = rj % 14 - ih_i + 15; }
                acc += qvw[tv] + qhw[th];
                s[jj] = acc * SCALE;
                mx = fmaxf(mx, s[jj]);
            } else s[jj] = -1e30f;
        }
        #pragma unroll
        for (int o = 16; o >= 1; o >>= 1) mx = fmaxf(mx, __shfl_xor_sync(0xffffffffu, mx, o));

        float sum = 0.f;
        #pragma unroll
        for (int jj = 0; jj < 7; jj++) {
            int j = lane + jj * 32;
            if (j < Nn) { s[jj] = __expf(s[jj] - mx); sum += s[jj]; }
            else s[jj] = 0.f;
        }
        #pragma unroll
        for (int o = 16; o >= 1; o >>= 1) sum += __shfl_xor_sync(0xffffffffu, sum, o);
        const float inv = 1.0f / sum;

        #pragma unroll
        for (int jj = 0; jj < 7; jj++) {
            int j = lane + jj * 32;
            if (j < Nn) pw[j] = s[jj] * inv;
        }
        __syncwarp();

        // deterministic bin sums for the value bias.
        // IDX_V(i, .) is constant over contiguous runs of 14; IDX_H(i, .) is 14-periodic.
        if (i == 0) {
            if (lane < NTAB) { svw[lane] = 0.f; shw[lane] = 0.f; }
            if (lane == 0) { svw[0] = 1.0f; shw[0] = 1.0f; }   // softmax row sums to 1
        } else if (lane < NTAB) {
            float sv = 0.f, sh = 0.f;
            int g = lane - 15 + iv_i;       // tv == lane  <=>  (j-1)/14 == g
            if (g >= 0 && g < 14) {
                int j0 = 14 * g + 1;
                #pragma unroll
                for (int u = 0; u < 14; u++) sv += pw[j0 + u];
            }
            int m = lane - 15 + ih_i;       // th == lane  <=>  (j-1)%14 == m
            if (m >= 0 && m < 14) {
                #pragma unroll
                for (int u = 0; u < 14; u++) sh += pw[1 + m + 14 * u];
            }
            if (lane == 0) { sv += pw[0]; sh += pw[0]; }   // j=0 -> bin 0 for both
            svw[lane] = sv;
            shw[lane] = sh;
        }
        __syncwarp();

        // output: split warp — half 0 handles j in [0,99), half 1 j in [99,197);
        // each half-lane owns a float4 of d (dl..dl+3). Combine via shfl_xor(16).
        float4 o4 = make_float4(0.f, 0.f, 0.f, 0.f);
        {
            const int j0 = half ? 99 : 0;
            const int j1 = half ? Nn : 99;
            #pragma unroll 4
            for (int j = j0; j < j1; j++) {
                float p = pw[j];
                float4 vv = *(const float4*)(Vs + j * KV_STRIDE + dl);
                o4.x += p * vv.x; o4.y += p * vv.y; o4.z += p * vv.z; o4.w += p * vv.w;
            }
            const int t0 = half * 15;
            #pragma unroll
            for (int t = t0; t < t0 + 15; t++) {
                float a = svw[t], c = shw[t];
                float4 vv = *(const float4*)(rvv_s + t * KV_STRIDE + dl);
                float4 hh = *(const float4*)(rvh_s + t * KV_STRIDE + dl);
                o4.x += a * vv.x + c * hh.x;
                o4.y += a * vv.y + c * hh.y;
                o4.z += a * vv.z + c * hh.z;
                o4.w += a * vv.w + c * hh.w;
            }
        }
        o4.x += __shfl_xor_sync(0xffffffffu, o4.x, 16);
        o4.y += __shfl_xor_sync(0xffffffffu, o4.y, 16);
        o4.z += __shfl_xor_sync(0xffffffffu, o4.z, 16);
        o4.w += __shfl_xor_sync(0xffffffffu, o4.w, 16);

        if (lane < 16) {
            size_t orow = ((size_t)(b * Nn + i)) * Dd + h * HDd;
            *(float4*)(g_o + orow + dl) = o4;
        }
        __syncwarp();
    }
}

// ---------------------------------------------------------------------------
// Launch
// ---------------------------------------------------------------------------
extern "C" void kernel_launch(void* const* d_in, const int* in_sizes, int n_in,
                              void* d_out, int out_size) {
    (void)in_sizes; (void)n_in; (void)out_size;
    const float* x   = (const float*)d_in[0];
    const float* wq  = (const float*)d_in[1];
    const float* bq  = (const float*)d_in[2];
    const float* wk  = (const float*)d_in[3];
    const float* bk  = (const float*)d_in[4];
    const float* wv  = (const float*)d_in[5];
    const float* bv  = (const float*)d_in[6];
    const float* wp  = (const float*)d_in[7];
    const float* bp  = (const float*)d_in[8];
    const float* rkv = (const float*)d_in[9];
    const float* rkh = (const float*)d_in[10];
    const float* rvv = (const float*)d_in[11];
    const float* rvh = (const float*)d_in[12];

    dim3 grid(Dd / 128, (MROWS + 127) / 128);  // (6, 99)
    dim3 block(256);
    sgemm_kernel<<<grid, block>>>(x, wq, bq, nullptr, MROWS, 1);
    sgemm_kernel<<<grid, block>>>(x, wk, bk, nullptr, MROWS, 2);
    sgemm_kernel<<<grid, block>>>(x, wv, bv, nullptr, MROWS, 3);

    size_t smem = (size_t)SMEM_FLOATS * sizeof(float);
    cudaFuncSetAttribute(attn_kernel, cudaFuncAttributeMaxDynamicSharedMemorySize, (int)smem);
    attn_kernel<<<Bb * Hh, 32 * NW, smem>>>(rkv, rkh, rvv, rvh);

    sgemm_kernel<<<grid, block>>>(nullptr, wp, bp, (float*)d_out, MROWS, 0);
}

// round 12
// speedup vs baseline: 1.4634x; 1.4402x over previous
#include <cuda_runtime.h>
#include <cuda_bf16.h>

// Problem constants
#define Bb 64
#define Nn 197
#define Dd 768
#define Hh 12
#define HDd 64
#define MROWS (Bb * Nn)          // 12608
#define NTAB 30
#define SCALE 0.125f

// ---------------------------------------------------------------------------
// Scratch (device globals)
// ---------------------------------------------------------------------------
__device__ float g_q[Bb * Hh * Nn * HDd];
__device__ float g_k[Bb * Hh * Nn * HDd];
__device__ float g_v[Bb * Hh * Nn * HDd];
__device__ float g_o[MROWS * Dd];

__device__ __nv_bfloat16 g_xh[MROWS * Dd];   // x split hi/lo
__device__ __nv_bfloat16 g_xl[MROWS * Dd];
__device__ __nv_bfloat16 g_oh[MROWS * Dd];   // attention-out split hi/lo
__device__ __nv_bfloat16 g_ol[MROWS * Dd];
__device__ __nv_bfloat16 g_wth[4][Dd * Dd];  // W^T hi/lo, [n][k] K-major
__device__ __nv_bfloat16 g_wtl[4][Dd * Dd];

// ---------------------------------------------------------------------------
// Warp-level MMA helpers (baseline PTX, sm_80+: valid for plain sm_103)
// ---------------------------------------------------------------------------
__device__ __forceinline__ unsigned smem_u32(const void* p) {
    unsigned a;
    asm("{ .reg .u64 t; cvta.to.shared.u64 t, %1; cvt.u32.u64 %0, t; }" : "=r"(a) : "l"(p));
    return a;
}
__device__ __forceinline__ void ldsm4(unsigned* r, unsigned addr) {
    asm volatile("ldmatrix.sync.aligned.m8n8.x4.shared.b16 {%0,%1,%2,%3}, [%4];"
                 : "=r"(r[0]), "=r"(r[1]), "=r"(r[2]), "=r"(r[3]) : "r"(addr));
}
__device__ __forceinline__ void ldsm2(unsigned* r, unsigned addr) {
    asm volatile("ldmatrix.sync.aligned.m8n8.x2.shared.b16 {%0,%1}, [%2];"
                 : "=r"(r[0]), "=r"(r[1]) : "r"(addr));
}
__device__ __forceinline__ void mma16816(float* d, const unsigned* a, const unsigned* b) {
    asm volatile(
        "mma.sync.aligned.m16n8k16.row.col.f32.bf16.bf16.f32 "
        "{%0,%1,%2,%3}, {%4,%5,%6,%7}, {%8,%9}, {%0,%1,%2,%3};"
        : "+f"(d[0]), "+f"(d[1]), "+f"(d[2]), "+f"(d[3])
        : "r"(a[0]), "r"(a[1]), "r"(a[2]), "r"(a[3]), "r"(b[0]), "r"(b[1]));
}

// ---------------------------------------------------------------------------
// Split fp32 -> (hi, lo) bf16.  dst_is_o: 1 = g_o -> g_oh/g_ol, 0 = src -> g_xh/g_xl
// ---------------------------------------------------------------------------
__global__ __launch_bounds__(256) void split_kernel(const float* __restrict__ src_in,
                                                    int dst_is_o, int n) {
    int i = blockIdx.x * 256 + threadIdx.x;
    if (i >= n) return;
    const float* src = dst_is_o ? g_o : src_in;
    __nv_bfloat16* ph = dst_is_o ? g_oh : g_xh;
    __nv_bfloat16* pl = dst_is_o ? g_ol : g_xl;
    float v = src[i];
    __nv_bfloat16 h = __float2bfloat16(v);
    ph[i] = h;
    pl[i] = __float2bfloat16(v - __bfloat162float(h));
}

// ---------------------------------------------------------------------------
// Transpose + split weights: W[k][n] f32 -> Wt_hi/lo[n][k] bf16 (slot 0..3)
// ---------------------------------------------------------------------------
__global__ __launch_bounds__(256) void tsplit_kernel(const float* __restrict__ W, int slot) {
    __shared__ float t[32][33];
    int n0 = blockIdx.x * 32, k0 = blockIdx.y * 32;
    int tx = threadIdx.x, ty = threadIdx.y;   // (32, 8)
    #pragma unroll
    for (int r = 0; r < 4; r++)
        t[ty + 8 * r][tx] = W[(size_t)(k0 + ty + 8 * r) * Dd + n0 + tx];
    __syncthreads();
    __nv_bfloat16* th = g_wth[slot];
    __nv_bfloat16* tl = g_wtl[slot];
    #pragma unroll
    for (int r = 0; r < 4; r++) {
        float v = t[tx][ty + 8 * r];   // = W[k0+tx][n0+ty+8r]
        __nv_bfloat16 h = __float2bfloat16(v);
        size_t o = (size_t)(n0 + ty + 8 * r) * Dd + k0 + tx;
        th[o] = h;
        tl[o] = __float2bfloat16(v - __bfloat162float(h));
    }
}

// ---------------------------------------------------------------------------
// mma.sync GEMM: C[M,768] = A[M,768] * W + bias  (bf16 hi/lo, 3 products)
// CTA: 128x128 tile, 8 warps (2m x 4n), warp tile 64x32, k-chunk 32.
// smem rows padded to 80B -> conflict-free ldmatrix.
// mode 0: out row-major; mode 1/2/3: scatter to g_q/g_k/g_v (B,H,N,HD).
// ---------------------------------------------------------------------------
#define KCB 32                    // k per chunk (bf16 elements)
#define NCH (Dd / KCB)            // 24
#define RSTRIDE 80                // bytes per smem row (32 bf16 + 16B pad)
#define TILE_SB (128 * RSTRIDE)   // 10240 B per tile
#define BUF_SB (4 * TILE_SB)      // Ah, Al, Bh, Bl
#define GEMM_SMEM (2 * BUF_SB)    // 81920 B

__global__ __launch_bounds__(256) void tc_gemm(const float* __restrict__ bias,
                                               float* __restrict__ out,
                                               int M, int mode, int wslot, int asrc) {
    extern __shared__ char smem[];
    const unsigned sb = smem_u32(smem);
    const int tid = threadIdx.x, warp = tid >> 5, lane = tid & 31;
    const int wm = warp >> 2, wn = warp & 3;
    const int m0 = blockIdx.y * 128, n0 = blockIdx.x * 128;

    const __nv_bfloat16* Ah = asrc ? g_oh : g_xh;
    const __nv_bfloat16* Al = asrc ? g_ol : g_xl;
    const __nv_bfloat16* Bh = g_wth[wslot];
    const __nv_bfloat16* Bl = g_wtl[wslot];

    float acc[4][4][4];
    #pragma unroll
    for (int a = 0; a < 4; a++)
        #pragma unroll
        for (int b = 0; b < 4; b++)
            #pragma unroll
            for (int c = 0; c < 4; c++) acc[a][b][c] = 0.f;

    // per-thread global-load map: 2048 uint4 per chunk over 256 threads = 8 each
    // idx = tid + it*256 ; tile = idx>>9 (0=Ah,1=Al,2=Bh,3=Bl), row = (idx>>2)&127, g = idx&3
    // prologue: load chunk 0 straight to smem buffer 0
    {
        #pragma unroll
        for (int it = 0; it < 8; it++) {
            int idx = tid + it * 256;
            int tile = idx >> 9, r = (idx >> 2) & 127, g = idx & 3;
            uint4 v = make_uint4(0, 0, 0, 0);
            if (tile == 0)      { if (m0 + r < M) v = ((const uint4*)(Ah + (size_t)(m0 + r) * Dd))[g]; }
            else if (tile == 1) { if (m0 + r < M) v = ((const uint4*)(Al + (size_t)(m0 + r) * Dd))[g]; }
            else if (tile == 2) v = ((const uint4*)(Bh + (size_t)(n0 + r) * Dd))[g];
            else                v = ((const uint4*)(Bl + (size_t)(n0 + r) * Dd))[g];
            *(uint4*)(smem + tile * TILE_SB + r * RSTRIDE + g * 16) = v;
        }
    }
    __syncthreads();

    for (int c = 0; c < NCH; c++) {
        const int cur = c & 1;
        const unsigned bb = sb + cur * BUF_SB;
        const bool more = (c + 1 < NCH);
        uint4 pf[8];
        if (more) {
            const int kc = (c + 1) * KCB;
            #pragma unroll
            for (int it = 0; it < 8; it++) {
                int idx = tid + it * 256;
                int tile = idx >> 9, r = (idx >> 2) & 127, g = idx & 3;
                uint4 v = make_uint4(0, 0, 0, 0);
                if (tile == 0)      { if (m0 + r < M) v = ((const uint4*)(Ah + (size_t)(m0 + r) * Dd + kc))[g]; }
                else if (tile == 1) { if (m0 + r < M) v = ((const uint4*)(Al + (size_t)(m0 + r) * Dd + kc))[g]; }
                else if (tile == 2) v = ((const uint4*)(Bh + (size_t)(n0 + r) * Dd + kc))[g];
                else                v = ((const uint4*)(Bl + (size_t)(n0 + r) * Dd + kc))[g];
                pf[it] = v;
            }
        }

        // compute this chunk: 2 k16 steps
        #pragma unroll
        for (int kb = 0; kb < 2; kb++) {
            unsigned ah[4][4], al[4][4];
            const int arow = (lane & 7) + ((lane >> 3) & 1) * 8;
            const unsigned acb = ((lane >> 4) & 1) * 16 + kb * 32;
            #pragma unroll
            for (int mt = 0; mt < 4; mt++) {
                unsigned aaddr = bb + (unsigned)((wm * 64 + mt * 16 + arow) * RSTRIDE) + acb;
                ldsm4(ah[mt], aaddr);
                ldsm4(al[mt], aaddr + TILE_SB);
            }
            const int nrow = wn * 32 + (lane & 7);
            const unsigned bcb = ((lane >> 3) & 1) * 16 + kb * 32;
            #pragma unroll
            for (int nt = 0; nt < 4; nt++) {
                unsigned baddr = bb + 2 * TILE_SB + (unsigned)((nrow + nt * 8) * RSTRIDE) + bcb;
                unsigned bh[2], bl[2];
                ldsm2(bh, baddr);
                ldsm2(bl, baddr + TILE_SB);
                #pragma unroll
                for (int mt = 0; mt < 4; mt++) {
                    mma16816(acc[mt][nt], ah[mt], bh);
                    mma16816(acc[mt][nt], ah[mt], bl);
                    mma16816(acc[mt][nt], al[mt], bh);
                }
            }
        }

        if (more) {
            char* nbuf = smem + (cur ^ 1) * BUF_SB;
            __syncthreads();   // everyone done reading the other buffer
            #pragma unroll
            for (int it = 0; it < 8; it++) {
                int idx = tid + it * 256;
                int tile = idx >> 9, r = (idx >> 2) & 127, g = idx & 3;
                *(uint4*)(nbuf + tile * TILE_SB + r * RSTRIDE + g * 16) = pf[it];
            }
            __syncthreads();
        }
    }

    // Epilogue: acc[mt][nt] rows wm*64+mt*16+{lane>>2, +8}, cols wn*32+nt*8+(lane&3)*2
    const int lr = lane >> 2, lc = (lane & 3) * 2;
    #pragma unroll
    for (int mt = 0; mt < 4; mt++) {
        #pragma unroll
        for (int nt = 0; nt < 4; nt++) {
            const int cgl = n0 + wn * 32 + nt * 8 + lc;
            const float b0 = bias[cgl], b1 = bias[cgl + 1];
            #pragma unroll
            for (int hrow = 0; hrow < 2; hrow++) {
                const int r = m0 + wm * 64 + mt * 16 + lr + hrow * 8;
                if (r >= M) continue;
                float2 o2;
                o2.x = acc[mt][nt][hrow * 2 + 0] + b0;
                o2.y = acc[mt][nt][hrow * 2 + 1] + b1;
                if (mode == 0) {
                    *(float2*)(out + (size_t)r * Dd + cgl) = o2;
                } else {
                    float* dst = (mode == 1) ? g_q : (mode == 2) ? g_k : g_v;
                    const int bidx = r / Nn, tok = r % Nn;
                    const int h = cgl >> 6, d = cgl & 63;
                    *(float2*)(dst + (((size_t)bidx * Hh + h) * Nn + tok) * HDd + d) = o2;
                }
            }
        }
    }
}

// ---------------------------------------------------------------------------
// Attention kernel (unchanged from R5): one CTA per (b,h), 16 warps
// ---------------------------------------------------------------------------
#define NW 16
#define KV_STRIDE 68
#define SMEM_FLOATS (2 * Nn * KV_STRIDE + 4 * NTAB * KV_STRIDE + NW * 64 + NW * 208 + 4 * NW * 32)

__global__ __launch_bounds__(32 * NW) void attn_kernel(
    const float* __restrict__ rkv, const float* __restrict__ rkh,
    const float* __restrict__ rvv, const float* __restrict__ rvh)
{
    extern __shared__ float sm[];
    float* Ks    = sm;
    float* Vs    = Ks + Nn * KV_STRIDE;
    float* rkv_s = Vs + Nn * KV_STRIDE;
    float* rkh_s = rkv_s + NTAB * KV_STRIDE;
    float* rvv_s = rkh_s + NTAB * KV_STRIDE;
    float* rvh_s = rvv_s + NTAB * KV_STRIDE;
    float* qs    = rvh_s + NTAB * KV_STRIDE;
    float* ps    = qs + NW * 64;
    float* qv_s  = ps + NW * 208;
    float* qh_s  = qv_s + NW * 32;
    float* sv_s  = qh_s + NW * 32;
    float* sh_s  = sv_s + NW * 32;

    const int bh   = blockIdx.x;
    const int tid  = threadIdx.x;
    const int warp = tid >> 5, lane = tid & 31;
    const size_t base = (size_t)bh * Nn * HDd;
    const int b = bh / Hh, h = bh % Hh;

    for (int idx = tid; idx < Nn * HDd; idx += 32 * NW) {
        int j = idx >> 6, d = idx & 63;
        Ks[j * KV_STRIDE + d] = g_k[base + idx];
        Vs[j * KV_STRIDE + d] = g_v[base + idx];
    }
    for (int idx = tid; idx < NTAB * HDd; idx += 32 * NW) {
        int t = idx >> 6, d = idx & 63;
        rkv_s[t * KV_STRIDE + d] = rkv[idx];
        rkh_s[t * KV_STRIDE + d] = rkh[idx];
        rvv_s[t * KV_STRIDE + d] = rvv[idx];
        rvh_s[t * KV_STRIDE + d] = rvh[idx];
    }
    __syncthreads();

    float* qw  = qs + warp * 64;
    float* pw  = ps + warp * 208;
    float* qvw = qv_s + warp * 32;
    float* qhw = qh_s + warp * 32;
    float* svw = sv_s + warp * 32;
    float* shw = sh_s + warp * 32;

    const int half = lane >> 4;
    const int dl   = (lane & 15) * 4;

    for (int i = warp; i < Nn; i += NW) {
        const float* qg = g_q + base + (size_t)i * HDd;
        qw[lane]      = qg[lane];
        qw[lane + 32] = qg[lane + 32];
        __syncwarp();

        float4 qreg[16];
        #pragma unroll
        for (int d4 = 0; d4 < 16; d4++) qreg[d4] = ((const float4*)qw)[d4];

        if (lane < NTAB) {
            float av = 0.f, ah = 0.f;
            const float4* tv4 = (const float4*)(rkv_s + lane * KV_STRIDE);
            const float4* th4 = (const float4*)(rkh_s + lane * KV_STRIDE);
            #pragma unroll
            for (int d4 = 0; d4 < 16; d4++) {
                float4 q4 = qreg[d4], v4 = tv4[d4], h4 = th4[d4];
                av += q4.x * v4.x + q4.y * v4.y + q4.z * v4.z + q4.w * v4.w;
                ah += q4.x * h4.x + q4.y * h4.y + q4.z * h4.z + q4.w * h4.w;
            }
            qvw[lane] = av;
            qhw[lane] = ah;
        }
        __syncwarp();

        const int iv_i = (i == 0) ? 0 : (i - 1) / 14;
        const int ih_i = (i == 0) ? 0 : (i - 1) % 14;

        float s[7];
        float mx = -1e30f;
        #pragma unroll
        for (int jj = 0; jj < 7; jj++) {
            int j = lane + jj * 32;
            if (j < Nn) {
                const float4* k4 = (const float4*)(Ks + j * KV_STRIDE);
                float acc = 0.f;
                #pragma unroll
                for (int d4 = 0; d4 < 16; d4++) {
                    float4 q4 = qreg[d4], kk4 = k4[d4];
                    acc += q4.x * kk4.x + q4.y * kk4.y + q4.z * kk4.z + q4.w * kk4.w;
                }
                int tv, th;
                if (i == 0 || j == 0) { tv = 0; th = 0; }
                else { int rj = j - 1; tv = rj / 14 - iv_i + 15; th = rj % 14 - ih_i + 15; }
                acc += qvw[tv] + qhw[th];
                s[jj] = acc * SCALE;
                mx = fmaxf(mx, s[jj]);
            } else s[jj] = -1e30f;
        }
        #pragma unroll
        for (int o = 16; o >= 1; o >>= 1) mx = fmaxf(mx, __shfl_xor_sync(0xffffffffu, mx, o));

        float sum = 0.f;
        #pragma unroll
        for (int jj = 0; jj < 7; jj++) {
            int j = lane + jj * 32;
            if (j < Nn) { s[jj] = __expf(s[jj] - mx); sum += s[jj]; }
            else s[jj] = 0.f;
        }
        #pragma unroll
        for (int o = 16; o >= 1; o >>= 1) sum += __shfl_xor_sync(0xffffffffu, sum, o);
        const float inv = 1.0f / sum;

        #pragma unroll
        for (int jj = 0; jj < 7; jj++) {
            int j = lane + jj * 32;
            if (j < Nn) pw[j] = s[jj] * inv;
        }
        __syncwarp();

        if (i == 0) {
            if (lane < NTAB) { svw[lane] = 0.f; shw[lane] = 0.f; }
            if (lane == 0) { svw[0] = 1.0f; shw[0] = 1.0f; }
        } else if (lane < NTAB) {
            float sv = 0.f, sh = 0.f;
            int g = lane - 15 + iv_i;
            if (g >= 0 && g < 14) {
                int j0 = 14 * g + 1;
                #pragma unroll
                for (int u = 0; u < 14; u++) sv += pw[j0 + u];
            }
            int m = lane - 15 + ih_i;
            if (m >= 0 && m < 14) {
                #pragma unroll
                for (int u = 0; u < 14; u++) sh += pw[1 + m + 14 * u];
            }
            if (lane == 0) { sv += pw[0]; sh += pw[0]; }
            svw[lane] = sv;
            shw[lane] = sh;
        }
        __syncwarp();

        float4 o4 = make_float4(0.f, 0.f, 0.f, 0.f);
        {
            const int j0 = half ? 99 : 0;
            const int j1 = half ? Nn : 99;
            #pragma unroll 4
            for (int j = j0; j < j1; j++) {
                float p = pw[j];
                float4 vv = *(const float4*)(Vs + j * KV_STRIDE + dl);
                o4.x += p * vv.x; o4.y += p * vv.y; o4.z += p * vv.z; o4.w += p * vv.w;
            }
            const int t0 = half * 15;
            #pragma unroll
            for (int t = t0; t < t0 + 15; t++) {
                float a = svw[t], c = shw[t];
                float4 vv = *(const float4*)(rvv_s + t * KV_STRIDE + dl);
                float4 hh = *(const float4*)(rvh_s + t * KV_STRIDE + dl);
                o4.x += a * vv.x + c * hh.x;
                o4.y += a * vv.y + c * hh.y;
                o4.z += a * vv.z + c * hh.z;
                o4.w += a * vv.w + c * hh.w;
            }
        }
        o4.x += __shfl_xor_sync(0xffffffffu, o4.x, 16);
        o4.y += __shfl_xor_sync(0xffffffffu, o4.y, 16);
        o4.z += __shfl_xor_sync(0xffffffffu, o4.z, 16);
        o4.w += __shfl_xor_sync(0xffffffffu, o4.w, 16);

        if (lane < 16) {
            size_t orow = ((size_t)(b * Nn + i)) * Dd + h * HDd;
            *(float4*)(g_o + orow + dl) = o4;
        }
        __syncwarp();
    }
}

// ---------------------------------------------------------------------------
// Launch
// ---------------------------------------------------------------------------
extern "C" void kernel_launch(void* const* d_in, const int* in_sizes, int n_in,
                              void* d_out, int out_size) {
    (void)in_sizes; (void)n_in; (void)out_size;
    const float* x   = (const float*)d_in[0];
    const float* wq  = (const float*)d_in[1];
    const float* bq  = (const float*)d_in[2];
    const float* wk  = (const float*)d_in[3];
    const float* bk  = (const float*)d_in[4];
    const float* wv  = (const float*)d_in[5];
    const float* bv  = (const float*)d_in[6];
    const float* wp  = (const float*)d_in[7];
    const float* bp  = (const float*)d_in[8];
    const float* rkv = (const float*)d_in[9];
    const float* rkh = (const float*)d_in[10];
    const float* rvv = (const float*)d_in[11];
    const float* rvh = (const float*)d_in[12];

    const int nel = MROWS * Dd;
    split_kernel<<<(nel + 255) / 256, 256>>>(x, 0, nel);
    tsplit_kernel<<<dim3(24, 24), dim3(32, 8)>>>(wq, 0);
    tsplit_kernel<<<dim3(24, 24), dim3(32, 8)>>>(wk, 1);
    tsplit_kernel<<<dim3(24, 24), dim3(32, 8)>>>(wv, 2);
    tsplit_kernel<<<dim3(24, 24), dim3(32, 8)>>>(wp, 3);

    cudaFuncSetAttribute(tc_gemm, cudaFuncAttributeMaxDynamicSharedMemorySize, GEMM_SMEM);
    dim3 gg(Dd / 128, (MROWS + 127) / 128);   // (6, 99)
    tc_gemm<<<gg, 256, GEMM_SMEM>>>(bq, nullptr, MROWS, 1, 0, 0);
    tc_gemm<<<gg, 256, GEMM_SMEM>>>(bk, nullptr, MROWS, 2, 1, 0);
    tc_gemm<<<gg, 256, GEMM_SMEM>>>(bv, nullptr, MROWS, 3, 2, 0);

    size_t smem = (size_t)SMEM_FLOATS * sizeof(float);
    cudaFuncSetAttribute(attn_kernel, cudaFuncAttributeMaxDynamicSharedMemorySize, (int)smem);
    attn_kernel<<<Bb * Hh, 32 * NW, smem>>>(rkv, rkh, rvv, rvh);

    split_kernel<<<(nel + 255) / 256, 256>>>(nullptr, 1, nel);
    tc_gemm<<<gg, 256, GEMM_SMEM>>>(bp, (float*)d_out, MROWS, 0, 3, 1);
}